// round 4
// baseline (speedup 1.0000x reference)
#include <cuda_runtime.h>
#include <cstdint>

#define N_GAUSS   16
#define N_ATOMS   3072
#define N_GRAPHS  64
#define K_GRID    4096

// Table: per atom, 512 cubic intervals over t = 8*r2; interval i covers
// t in [i-0.5, i+0.5], local parameter v = t-(i-0.5) in [0,1].
#define NNODES    512
#define TSCALE    8.0f
#define TCLAMP    511.49f

#define BLOCK     512
#define PPT       2
#define CHUNK     (BLOCK*PPT)       // 1024
#define NCHUNK    (K_GRID/CHUNK)    // 4

#define ACAP      256               // atom-coord smem capacity per tile
#define NBUF      3                 // table ring buffers

__device__ int    g_start[N_GRAPHS + 1];
__device__ float4 g_table[N_ATOMS * NNODES];   // ~25 MB scratch

__device__ __forceinline__ float ex2f(float x) {
    float y; asm("ex2.approx.ftz.f32 %0, %1;" : "=f"(y) : "f"(x)); return y;
}

__device__ __forceinline__ void cpa16(void* dst_smem, const void* src_gmem) {
    uint32_t d = (uint32_t)__cvta_generic_to_shared(dst_smem);
    asm volatile("cp.async.cg.shared.global [%0], [%1], 16;" :: "r"(d), "l"(src_gmem));
}
__device__ __forceinline__ void cpa_commit() { asm volatile("cp.async.commit_group;"); }
__device__ __forceinline__ void cpa_wait1()  { asm volatile("cp.async.wait_group 1;"); }

// ---------------------------------------------------------------------------
// Prep: detect batch dtype (int64 vs int32), binary-search per-graph ranges.
__global__ void prep_kernel(const int* __restrict__ braw) {
    __shared__ int any_odd_nonzero;
    if (threadIdx.x == 0) any_odd_nonzero = 0;
    __syncthreads();
    int local = 0;
    for (int i = 1 + 2 * (int)threadIdx.x; i < N_ATOMS; i += 2 * (int)blockDim.x)
        local |= braw[i];
    if (local) atomicOr(&any_odd_nonzero, 1);
    __syncthreads();
    const bool is32 = (any_odd_nonzero != 0);
    if (threadIdx.x <= N_GRAPHS) {
        int g = threadIdx.x;
        int lo = 0, hi = N_ATOMS;
        while (lo < hi) {
            int m = (lo + hi) >> 1;
            int v = is32 ? braw[m] : braw[2 * m];
            if (v < g) lo = m + 1; else hi = m;
        }
        g_start[g] = lo;
    }
}

// ---------------------------------------------------------------------------
// Build: per-atom Hermite-cubic table. Node k at t = k-0.5 (r2 = t/8).
__global__ __launch_bounds__(128)
void build_kernel(const float* __restrict__ coeff) {
    const int atom = blockIdx.x;
    __shared__ float w[N_GAUSS], wc[N_GAUSS];
    __shared__ float fv[NNODES + 1], mv[NNODES + 1];

    if (threadIdx.x < N_GAUSS) {
        int j = threadIdx.x;
        float sigma = 0.5f + 0.3f * (float)j;
        float tt = sigma * 2.5066282746310002f;      // sigma*sqrt(2*pi)
        float sr = 1.0f / (tt * tt * tt);
        float cj = 1.0f / (sigma * sigma);
        float wj = coeff[atom * N_GAUSS + j] * sr;
        w[j]  = wj;
        wc[j] = wj * cj * (1.0f / TSCALE);           // df/dt = -sum wc*e
    }
    __syncthreads();

    for (int k = threadIdx.x; k <= NNODES; k += 128) {
        float r2 = ((float)k - 0.5f) * (1.0f / TSCALE);
        float s1 = 0.f, s2 = 0.f;
        #pragma unroll
        for (int j = 0; j < N_GAUSS; j++) {
            float sigma = 0.5f + 0.3f * (float)j;
            float cL = 1.4426950408889634f / (sigma * sigma);  // log2e/sigma^2
            float e = ex2f(-r2 * cL);
            s1 = fmaf(w[j],  e, s1);
            s2 = fmaf(wc[j], e, s2);
        }
        fv[k] = s1;
        mv[k] = -s2;
    }
    __syncthreads();

    for (int i = threadIdx.x; i < NNODES; i += 128) {
        float fL = fv[i], fR = fv[i + 1];
        float mL = mv[i], mR = mv[i + 1];
        float dd = fR - fL;
        float4 c;
        c.x = fL;
        c.y = mL;
        c.z = 3.0f * dd - 2.0f * mL - mR;
        c.w = mL + mR - 2.0f * dd;
        g_table[(size_t)atom * NNODES + i] = c;
    }
}

// ---------------------------------------------------------------------------
// Density: per grid point, sum f_a(r2) over the graph's atoms via smem-staged
// cubic tables. 3-buffer cp.async ring; prefetch issued AFTER the barrier so
// the buffer being overwritten (last read one iteration ago) is protected.
__global__ __launch_bounds__(BLOCK)
void density_kernel(const float* __restrict__ atom_coord,
                    const float* __restrict__ grid,
                    float* __restrict__ out) {
    __shared__ float4 tbl[NBUF][NNODES];              // 24 KB
    __shared__ float  sax[ACAP], say[ACAP], saz[ACAP];

    const int g   = blockIdx.y;
    const int tid = threadIdx.x;
    const int k0  = blockIdx.x * CHUNK + tid;
    const int k1  = k0 + BLOCK;

    const int start = g_start[g];
    const int n     = g_start[g + 1] - start;

    const float S = 2.8284271247461903f;  // sqrt(8): t = |S*(p-a)|^2 = 8*r2

    const float* gp = grid + (size_t)g * K_GRID * 3;
    const float px0 = gp[k0 * 3 + 0] * S, py0 = gp[k0 * 3 + 1] * S, pz0 = gp[k0 * 3 + 2] * S;
    const float px1 = gp[k1 * 3 + 0] * S, py1 = gp[k1 * 3 + 1] * S, pz1 = gp[k1 * 3 + 2] * S;

    float acc0 = 0.f, acc1 = 0.f;

    for (int base = 0; base < n; base += ACAP) {
        const int cnt = min(ACAP, n - base);
        const float4* src = g_table + (size_t)(start + base) * NNODES + tid;

        __syncthreads();  // previous tile fully consumed
        for (int a = tid; a < cnt; a += BLOCK) {
            const float* ac = atom_coord + (size_t)(start + base + a) * 3;
            sax[a] = ac[0] * S;
            say[a] = ac[1] * S;
            saz[a] = ac[2] * S;
        }

        // Prime: atoms 0 and 1 (always commit to keep group count invariant).
        cpa16(&tbl[0][tid], src);
        cpa_commit();
        if (1 < cnt) cpa16(&tbl[1][tid], src + NNODES);
        cpa_commit();
        __syncthreads();  // coords visible

        int buf = 0;
        for (int a = 0; a < cnt; a++) {
            cpa_wait1();      // my copies for atom a complete
            __syncthreads();  // everyone's atom-a copies visible; prior readers
                              // of the buffer we're about to refill are done
            if (a + 2 < cnt)
                cpa16(&tbl[(buf + 2 >= NBUF) ? buf + 2 - NBUF : buf + 2][tid],
                      src + (size_t)(a + 2) * NNODES);
            cpa_commit();

            const float ax = sax[a], ay = say[a], az = saz[a];
            {
                float dx = px0 - ax, dy = py0 - ay, dz = pz0 - az;
                float t = fmaf(dx, dx, fmaf(dy, dy, dz * dz));
                t = fminf(t, TCLAMP);
                float m = t + 8388608.0f;                 // round(t) via 2^23
                int   i = __float_as_int(m) & 0x3FF;
                // v = t - (i - 0.5). NOTE: (m - 8388608.0f) == (float)i exactly;
                // 8388608.5f is NOT representable (ulp=1 at 2^23) — do NOT fold.
                float v = (t - (m - 8388608.0f)) + 0.5f;  // in [0,1]
                float4 c = tbl[buf][i];
                acc0 += fmaf(fmaf(fmaf(c.w, v, c.z), v, c.y), v, c.x);
            }
            {
                float dx = px1 - ax, dy = py1 - ay, dz = pz1 - az;
                float t = fmaf(dx, dx, fmaf(dy, dy, dz * dz));
                t = fminf(t, TCLAMP);
                float m = t + 8388608.0f;
                int   i = __float_as_int(m) & 0x3FF;
                float v = (t - (m - 8388608.0f)) + 0.5f;
                float4 c = tbl[buf][i];
                acc1 += fmaf(fmaf(fmaf(c.w, v, c.z), v, c.y), v, c.x);
            }

            buf = (buf + 1 >= NBUF) ? 0 : buf + 1;
        }
    }

    out[(size_t)g * K_GRID + k0] = acc0;
    out[(size_t)g * K_GRID + k1] = acc1;
}

// ---------------------------------------------------------------------------
extern "C" void kernel_launch(void* const* d_in, const int* in_sizes, int n_in,
                              void* d_out, int out_size) {
    const float* coeff      = (const float*)d_in[0];
    const float* atom_coord = (const float*)d_in[1];
    const float* grid       = (const float*)d_in[2];
    const int*   batch_raw  = (const int*)d_in[3];
    float* out = (float*)d_out;

    prep_kernel<<<1, 128>>>(batch_raw);
    build_kernel<<<N_ATOMS, 128>>>(coeff);
    density_kernel<<<dim3(NCHUNK, N_GRAPHS), BLOCK>>>(atom_coord, grid, out);
}

// round 5
// speedup vs baseline: 1.1381x; 1.1381x over previous
#include <cuda_runtime.h>
#include <cstdint>

#define N_GAUSS   16
#define N_ATOMS   3072
#define N_GRAPHS  64
#define K_GRID    4096

// Table: per atom, 512 cubic intervals over t = 8*r2. Interval i = round(t)
// covers t in [i-0.5, i+0.5]; local parameter u = t - i in [-0.5, 0.5].
#define NNODES    512
#define TSCALE    8.0f
#define TCLAMP    511.49f

#define BLOCK     512
#define PPT       4
#define CHUNK     (BLOCK*PPT)       // 2048
#define NCHUNK    (K_GRID/CHUNK)    // 2  -> 128 blocks

#define ACAP      1024              // atom-coord smem per tile (covers n<=1024/tile)

__device__ float4 g_table[N_ATOMS * NNODES];   // ~25 MB scratch

__device__ __forceinline__ float ex2f(float x) {
    float y; asm("ex2.approx.ftz.f32 %0, %1;" : "=f"(y) : "f"(x)); return y;
}
__device__ __forceinline__ void cpa16(void* dst_smem, const void* src_gmem) {
    uint32_t d = (uint32_t)__cvta_generic_to_shared(dst_smem);
    asm volatile("cp.async.cg.shared.global [%0], [%1], 16;" :: "r"(d), "l"(src_gmem));
}
__device__ __forceinline__ void cpa_commit() { asm volatile("cp.async.commit_group;"); }
__device__ __forceinline__ void cpa_wait0()  { asm volatile("cp.async.wait_group 0;"); }

// ---------------------------------------------------------------------------
// Build: per-atom center-shifted Hermite-cubic table. Node k at t = k-0.5.
__global__ __launch_bounds__(128)
void build_kernel(const float* __restrict__ coeff) {
    const int atom = blockIdx.x;
    __shared__ float w[N_GAUSS], wc[N_GAUSS];
    __shared__ float fv[NNODES + 1], mv[NNODES + 1];

    if (threadIdx.x < N_GAUSS) {
        int j = threadIdx.x;
        float sigma = 0.5f + 0.3f * (float)j;
        float tt = sigma * 2.5066282746310002f;      // sigma*sqrt(2*pi)
        float sr = 1.0f / (tt * tt * tt);
        float cj = 1.0f / (sigma * sigma);
        float wj = coeff[atom * N_GAUSS + j] * sr;
        w[j]  = wj;
        wc[j] = wj * cj * (1.0f / TSCALE);           // df/dt = -sum wc*e
    }
    __syncthreads();

    for (int k = threadIdx.x; k <= NNODES; k += 128) {
        float r2 = ((float)k - 0.5f) * (1.0f / TSCALE);
        float s1 = 0.f, s2 = 0.f;
        #pragma unroll
        for (int j = 0; j < N_GAUSS; j++) {
            float sigma = 0.5f + 0.3f * (float)j;
            float cL = 1.4426950408889634f / (sigma * sigma);  // log2e/sigma^2
            float e = ex2f(-r2 * cL);
            s1 = fmaf(w[j],  e, s1);
            s2 = fmaf(wc[j], e, s2);
        }
        fv[k] = s1;
        mv[k] = -s2;
    }
    __syncthreads();

    for (int i = threadIdx.x; i < NNODES; i += 128) {
        float fL = fv[i], fR = fv[i + 1];
        float mL = mv[i], mR = mv[i + 1];
        float dd = fR - fL;
        // Hermite in v = u+0.5 over [0,1]:
        float a0 = fL, a1 = mL;
        float a2 = 3.0f * dd - 2.0f * mL - mR;
        float a3 = mL + mR - 2.0f * dd;
        // Shift to u in [-0.5, 0.5]:
        float4 c;
        c.x = a0 + 0.5f * a1 + 0.25f * a2 + 0.125f * a3;
        c.y = a1 + a2 + 0.75f * a3;
        c.z = a2 + 1.5f * a3;
        c.w = a3;
        g_table[(size_t)atom * NNODES + i] = c;
    }
}

// ---------------------------------------------------------------------------
// Density: 128 blocks (2 chunks x 64 graphs), 512 threads, 4 points/thread.
// Per-block inline batch-range scan (replaces prep kernel). Atom tables staged
// 2-at-a-time via cp.async double buffer (wait -> sync -> issue ordering).
__global__ __launch_bounds__(BLOCK)
void density_kernel(const float* __restrict__ atom_coord,
                    const float* __restrict__ grid,
                    const int* __restrict__ braw,
                    float* __restrict__ out) {
    __shared__ float4 tbl[2][2][NNODES];              // 32 KB
    __shared__ float  sax[ACAP], say[ACAP], saz[ACAP];
    __shared__ int s_flag, s_start, s_end;

    const int g   = blockIdx.y;
    const int tid = threadIdx.x;

    if (tid == 0) { s_flag = 0; s_start = N_ATOMS; s_end = N_ATOMS; }
    __syncthreads();

    // dtype detect: int64 batch has all-zero odd words (values in [0,64)).
    // Only scan odd indices < N_ATOMS: in-bounds for int32 too.
    int loc = 0;
    for (int i = 1 + 2 * tid; i < N_ATOMS; i += 2 * BLOCK) loc |= braw[i];
    if (loc) atomicOr(&s_flag, 1);
    __syncthreads();
    const bool is32 = (s_flag != 0);

    // One-pass transition scan: start = first i with b[i]>=g, end = first i
    // with b[i]>=g+1 (batch sorted => unique writers, plain stores).
    for (int i = tid; i < N_ATOMS; i += BLOCK) {
        int bi = is32 ? braw[i] : braw[2 * i];
        int bp = (i == 0) ? -1 : (is32 ? braw[i - 1] : braw[2 * i - 2]);
        if (bi >= g     && bp < g)     s_start = i;
        if (bi >= g + 1 && bp < g + 1) s_end   = i;
    }
    __syncthreads();
    const int start = s_start;
    const int n     = s_end - start;

    const float S = 2.8284271247461903f;  // sqrt(8): t = |S*(p-a)|^2 = 8*r2
    const float* gp = grid + (size_t)g * K_GRID * 3;
    const int kb = blockIdx.x * CHUNK + tid;

    float px[PPT], py[PPT], pz[PPT], acc[PPT];
    #pragma unroll
    for (int q = 0; q < PPT; q++) {
        const int k = kb + q * BLOCK;
        px[q] = gp[k * 3 + 0] * S;
        py[q] = gp[k * 3 + 1] * S;
        pz[q] = gp[k * 3 + 2] * S;
        acc[q] = 0.f;
    }

    for (int base = 0; base < n; base += ACAP) {
        const int cnt = min(ACAP, n - base);
        const int A0  = start + base;
        const float4* src = g_table + (size_t)A0 * NNODES + tid;

        __syncthreads();  // previous tile (tables + coords) fully consumed
        for (int a = tid; a < cnt; a += BLOCK) {
            const float* ac = atom_coord + (size_t)(A0 + a) * 3;
            sax[a] = ac[0] * S;
            say[a] = ac[1] * S;
            saz[a] = ac[2] * S;
        }

        // Prime step 0 (atoms 0, min(1,cnt-1)).
        cpa16(&tbl[0][0][tid], src);
        cpa16(&tbl[0][1][tid], src + (size_t)min(1, cnt - 1) * NNODES);
        cpa_commit();

        const int steps = (cnt + 1) >> 1;
        for (int s = 0; s < steps; s++) {
            const int buf = s & 1;
            cpa_wait0();      // step-s tables (issued last) complete for me
            __syncthreads();  // complete for all; prior readers of buf^1 done
            if (s + 1 < steps) {
                const int a0 = 2 * (s + 1);
                const int a1 = min(a0 + 1, cnt - 1);
                cpa16(&tbl[buf ^ 1][0][tid], src + (size_t)a0 * NNODES);
                cpa16(&tbl[buf ^ 1][1][tid], src + (size_t)a1 * NNODES);
            }
            cpa_commit();

            const int a0 = 2 * s;
            {
                const float ax = sax[a0], ay = say[a0], az = saz[a0];
                #pragma unroll
                for (int q = 0; q < PPT; q++) {
                    float dx = px[q] - ax, dy = py[q] - ay, dz = pz[q] - az;
                    float t = fmaf(dx, dx, fmaf(dy, dy, dz * dz));
                    t = fminf(t, TCLAMP);
                    float m = t + 8388608.0f;            // round(t) via 2^23
                    int   i = __float_as_int(m) & 0x3FF;
                    float u = t - (m - 8388608.0f);      // in [-0.5, 0.5]
                    float4 c = tbl[buf][0][i];
                    acc[q] += fmaf(fmaf(fmaf(c.w, u, c.z), u, c.y), u, c.x);
                }
            }
            if (a0 + 1 < cnt) {
                const float ax = sax[a0 + 1], ay = say[a0 + 1], az = saz[a0 + 1];
                #pragma unroll
                for (int q = 0; q < PPT; q++) {
                    float dx = px[q] - ax, dy = py[q] - ay, dz = pz[q] - az;
                    float t = fmaf(dx, dx, fmaf(dy, dy, dz * dz));
                    t = fminf(t, TCLAMP);
                    float m = t + 8388608.0f;
                    int   i = __float_as_int(m) & 0x3FF;
                    float u = t - (m - 8388608.0f);
                    float4 c = tbl[buf][1][i];
                    acc[q] += fmaf(fmaf(fmaf(c.w, u, c.z), u, c.y), u, c.x);
                }
            }
        }
    }

    float* op = out + (size_t)g * K_GRID;
    #pragma unroll
    for (int q = 0; q < PPT; q++)
        op[kb + q * BLOCK] = acc[q];
}

// ---------------------------------------------------------------------------
extern "C" void kernel_launch(void* const* d_in, const int* in_sizes, int n_in,
                              void* d_out, int out_size) {
    const float* coeff      = (const float*)d_in[0];
    const float* atom_coord = (const float*)d_in[1];
    const float* grid       = (const float*)d_in[2];
    const int*   batch_raw  = (const int*)d_in[3];
    float* out = (float*)d_out;

    build_kernel<<<N_ATOMS, 128>>>(coeff);
    density_kernel<<<dim3(NCHUNK, N_GRAPHS), BLOCK>>>(atom_coord, grid, batch_raw, out);
}

// round 6
// speedup vs baseline: 1.2197x; 1.0717x over previous
#include <cuda_runtime.h>
#include <cstdint>

#define N_GAUSS   16
#define N_ATOMS   3072
#define N_GRAPHS  64
#define K_GRID    4096

// Table: per atom, 512 cubic intervals over t = 8*r2. Interval i = round(t)
// covers t in [i-0.5, i+0.5]; local parameter u = t - i in [-0.5, 0.5].
#define NNODES    512
#define TSCALE    8.0f
#define TCLAMP    511.49f
#define ABYTES    (NNODES * 16)     // 8 KB per atom table

#define BLOCK     512
#define PPT       2
#define CHUNK     (BLOCK*PPT)       // 1024
#define NCHUNK    (K_GRID/CHUNK)    // 4  -> 256 blocks (2 resident/SM)

#define GROUP     2                 // atoms per pipeline step
#define NBUF      2
#define ACAP      1024              // atom-coord smem per tile

__device__ float4 g_table[N_ATOMS * NNODES];   // ~25 MB scratch

__device__ __forceinline__ float ex2f(float x) {
    float y; asm("ex2.approx.ftz.f32 %0, %1;" : "=f"(y) : "f"(x)); return y;
}
__device__ __forceinline__ uint32_t s2u(const void* p) {
    return (uint32_t)__cvta_generic_to_shared(p);
}
__device__ __forceinline__ void mbar_init(uint32_t a, uint32_t cnt) {
    asm volatile("mbarrier.init.shared.b64 [%0], %1;" :: "r"(a), "r"(cnt) : "memory");
}
__device__ __forceinline__ void mbar_expect_tx(uint32_t a, uint32_t tx) {
    asm volatile("mbarrier.arrive.expect_tx.shared.b64 _, [%0], %1;" :: "r"(a), "r"(tx) : "memory");
}
__device__ __forceinline__ void bulk_g2s(uint32_t dst, const void* src,
                                         uint32_t sz, uint32_t mbar) {
    asm volatile("cp.async.bulk.shared::cluster.global.mbarrier::complete_tx::bytes"
                 " [%0], [%1], %2, [%3];"
                 :: "r"(dst), "l"(src), "r"(sz), "r"(mbar) : "memory");
}
__device__ __forceinline__ void mbar_wait(uint32_t mbar, uint32_t phase) {
    asm volatile(
        "{\n\t"
        ".reg .pred P;\n\t"
        "WAIT_%=:\n\t"
        "mbarrier.try_wait.parity.acquire.cta.shared::cta.b64 P, [%0], %1;\n\t"
        "@P bra.uni DONE_%=;\n\t"
        "bra.uni WAIT_%=;\n\t"
        "DONE_%=:\n\t"
        "}" :: "r"(mbar), "r"(phase) : "memory");
}

// ---------------------------------------------------------------------------
// Build: per-atom center-shifted Hermite-cubic table. Node k at t = k-0.5.
__global__ __launch_bounds__(128)
void build_kernel(const float* __restrict__ coeff) {
    const int atom = blockIdx.x;
    __shared__ float w[N_GAUSS], wc[N_GAUSS];
    __shared__ float fv[NNODES + 1], mv[NNODES + 1];

    if (threadIdx.x < N_GAUSS) {
        int j = threadIdx.x;
        float sigma = 0.5f + 0.3f * (float)j;
        float tt = sigma * 2.5066282746310002f;      // sigma*sqrt(2*pi)
        float sr = 1.0f / (tt * tt * tt);
        float cj = 1.0f / (sigma * sigma);
        float wj = coeff[atom * N_GAUSS + j] * sr;
        w[j]  = wj;
        wc[j] = wj * cj * (1.0f / TSCALE);           // df/dt = -sum wc*e
    }
    __syncthreads();

    for (int k = threadIdx.x; k <= NNODES; k += 128) {
        float r2 = ((float)k - 0.5f) * (1.0f / TSCALE);
        float s1 = 0.f, s2 = 0.f;
        #pragma unroll
        for (int j = 0; j < N_GAUSS; j++) {
            float sigma = 0.5f + 0.3f * (float)j;
            float cL = 1.4426950408889634f / (sigma * sigma);  // log2e/sigma^2
            float e = ex2f(-r2 * cL);
            s1 = fmaf(w[j],  e, s1);
            s2 = fmaf(wc[j], e, s2);
        }
        fv[k] = s1;
        mv[k] = -s2;
    }
    __syncthreads();

    for (int i = threadIdx.x; i < NNODES; i += 128) {
        float fL = fv[i], fR = fv[i + 1];
        float mL = mv[i], mR = mv[i + 1];
        float dd = fR - fL;
        float a0 = fL, a1 = mL;
        float a2 = 3.0f * dd - 2.0f * mL - mR;
        float a3 = mL + mR - 2.0f * dd;
        // Shift Hermite basis from v in [0,1] to u = v-0.5 in [-0.5,0.5]:
        float4 c;
        c.x = a0 + 0.5f * a1 + 0.25f * a2 + 0.125f * a3;
        c.y = a1 + a2 + 0.75f * a3;
        c.z = a2 + 1.5f * a3;
        c.w = a3;
        g_table[(size_t)atom * NNODES + i] = c;
    }
}

// ---------------------------------------------------------------------------
// Density: 256 blocks (4 chunks x 64 graphs), 512 threads, 2 points/thread.
// Tables staged GROUP atoms at a time with one cp.async.bulk + mbarrier.
__global__ __launch_bounds__(BLOCK)
void density_kernel(const float* __restrict__ atom_coord,
                    const float* __restrict__ grid,
                    const int* __restrict__ braw,
                    float* __restrict__ out) {
    __shared__ __align__(16) float4 tbl[NBUF][GROUP][NNODES];   // 32 KB
    __shared__ float  sax[ACAP], say[ACAP], saz[ACAP];          // 12 KB
    __shared__ __align__(8) unsigned long long mbar[NBUF];
    __shared__ int s_flag, s_start, s_end;

    const int g   = blockIdx.y;
    const int tid = threadIdx.x;
    const uint32_t mb0 = s2u(&mbar[0]);
    const uint32_t mb1 = s2u(&mbar[1]);

    if (tid == 0) {
        s_flag = 0; s_start = N_ATOMS; s_end = N_ATOMS;
        mbar_init(mb0, 1);
        mbar_init(mb1, 1);
        asm volatile("fence.proxy.async.shared::cta;" ::: "memory");
    }
    __syncthreads();

    // dtype detect: int64 batch (values < 64) has all-zero odd words.
    int loc = 0;
    for (int i = 1 + 2 * tid; i < N_ATOMS; i += 2 * BLOCK) loc |= braw[i];
    if (loc) atomicOr(&s_flag, 1);
    __syncthreads();
    const bool is32 = (s_flag != 0);

    // Transition scan: start = first i with b[i]>=g, end = first with b[i]>=g+1.
    for (int i = tid; i < N_ATOMS; i += BLOCK) {
        int bi = is32 ? braw[i] : braw[2 * i];
        int bp = (i == 0) ? -1 : (is32 ? braw[i - 1] : braw[2 * i - 2]);
        if (bi >= g     && bp < g)     s_start = i;
        if (bi >= g + 1 && bp < g + 1) s_end   = i;
    }
    __syncthreads();
    const int start = s_start;
    const int n     = s_end - start;

    const float S = 2.8284271247461903f;  // sqrt(8): t = |S*(p-a)|^2 = 8*r2
    const float* gp = grid + (size_t)g * K_GRID * 3;
    const int kb = blockIdx.x * CHUNK + tid;

    float px[PPT], py[PPT], pz[PPT], acc[PPT];
    #pragma unroll
    for (int q = 0; q < PPT; q++) {
        const int k = kb + q * BLOCK;
        px[q] = gp[k * 3 + 0] * S;
        py[q] = gp[k * 3 + 1] * S;
        pz[q] = gp[k * 3 + 2] * S;
        acc[q] = 0.f;
    }

    uint32_t ph0 = 0, ph1 = 0;   // mbarrier phase parities (uniform across threads)

    for (int base = 0; base < n; base += ACAP) {
        const int cnt = min(ACAP, n - base);
        const int A0  = start + base;
        const float4* src = g_table + (size_t)A0 * NNODES;

        __syncthreads();  // previous tile fully consumed
        for (int a = tid; a < cnt; a += BLOCK) {
            const float* ac = atom_coord + (size_t)(A0 + a) * 3;
            sax[a] = ac[0] * S;
            say[a] = ac[1] * S;
            saz[a] = ac[2] * S;
        }
        __syncthreads();  // coords visible (and tbl safe to overwrite)

        const int steps = (cnt + GROUP - 1) / GROUP;

        if (tid == 0) {
            // Prime up to 2 steps.
            {
                uint32_t sz = (uint32_t)min(GROUP, cnt) * ABYTES;
                mbar_expect_tx(mb0, sz);
                bulk_g2s(s2u(&tbl[0][0][0]), src, sz, mb0);
            }
            if (steps > 1) {
                uint32_t sz = (uint32_t)min(GROUP, cnt - GROUP) * ABYTES;
                mbar_expect_tx(mb1, sz);
                bulk_g2s(s2u(&tbl[1][0][0]), src + (size_t)GROUP * NNODES, sz, mb1);
            }
        }

        for (int s = 0; s < steps; s++) {
            const int buf = s & 1;
            // Wait for this step's tables.
            if (buf == 0) { mbar_wait(mb0, ph0); ph0 ^= 1; }
            else          { mbar_wait(mb1, ph1); ph1 ^= 1; }

            const int a0 = s * GROUP;
            {
                const float ax = sax[a0], ay = say[a0], az = saz[a0];
                #pragma unroll
                for (int q = 0; q < PPT; q++) {
                    float dx = px[q] - ax, dy = py[q] - ay, dz = pz[q] - az;
                    float t = fmaf(dx, dx, fmaf(dy, dy, dz * dz));
                    t = fminf(t, TCLAMP);
                    float m = t + 8388608.0f;            // round(t) via 2^23
                    int   i = __float_as_int(m) & 0x3FF;
                    float u = t - (m - 8388608.0f);      // in [-0.5, 0.5]
                    float4 c = tbl[buf][0][i];
                    acc[q] += fmaf(fmaf(fmaf(c.w, u, c.z), u, c.y), u, c.x);
                }
            }
            if (a0 + 1 < cnt) {
                const float ax = sax[a0 + 1], ay = say[a0 + 1], az = saz[a0 + 1];
                #pragma unroll
                for (int q = 0; q < PPT; q++) {
                    float dx = px[q] - ax, dy = py[q] - ay, dz = pz[q] - az;
                    float t = fmaf(dx, dx, fmaf(dy, dy, dz * dz));
                    t = fminf(t, TCLAMP);
                    float m = t + 8388608.0f;
                    int   i = __float_as_int(m) & 0x3FF;
                    float u = t - (m - 8388608.0f);
                    float4 c = tbl[buf][1][i];
                    acc[q] += fmaf(fmaf(fmaf(c.w, u, c.z), u, c.y), u, c.x);
                }
            }

            __syncthreads();  // all reads of tbl[buf] complete
            if (tid == 0 && s + 2 < steps) {
                const int an = (s + 2) * GROUP;
                uint32_t sz = (uint32_t)min(GROUP, cnt - an) * ABYTES;
                uint32_t mb = buf ? mb1 : mb0;
                mbar_expect_tx(mb, sz);
                bulk_g2s(s2u(&tbl[buf][0][0]), src + (size_t)an * NNODES, sz, mb);
            }
        }
    }

    float* op = out + (size_t)g * K_GRID;
    #pragma unroll
    for (int q = 0; q < PPT; q++)
        op[kb + q * BLOCK] = acc[q];
}

// ---------------------------------------------------------------------------
extern "C" void kernel_launch(void* const* d_in, const int* in_sizes, int n_in,
                              void* d_out, int out_size) {
    const float* coeff      = (const float*)d_in[0];
    const float* atom_coord = (const float*)d_in[1];
    const float* grid       = (const float*)d_in[2];
    const int*   batch_raw  = (const int*)d_in[3];
    float* out = (float*)d_out;

    build_kernel<<<N_ATOMS, 128>>>(coeff);
    density_kernel<<<dim3(NCHUNK, N_GRAPHS), BLOCK>>>(atom_coord, grid, batch_raw, out);
}